// round 15
// baseline (speedup 1.0000x reference)
#include <cuda_runtime.h>
#include <cuda_fp16.h>
#include <cstdint>

#define D_MODEL 1024
#define BATCH   4
#define SEQ     4096
#define M_TOTAL (BATCH*SEQ)
#define NX      (M_TOTAL*D_MODEL)      // 16M
#define D2      (D_MODEL*D_MODEL)      // 1M

#define CHUNK  32
#define NCHUNK (SEQ/CHUNK)   // 128

// ---------------- scratch (__device__ globals, allocation-free rule)
__device__ __half g_xh[NX];            // x (half); reused as v (half) after GEMM2
__device__ __half g_uh[NX];            // u (half) after GEMM1
__device__ __half g_w1h[D2];
__device__ __half g_w2h[D2];
__device__ float  g_C  [BATCH*NCHUNK*D_MODEL];
__device__ float  g_cin[BATCH*NCHUNK*D_MODEL];

// ---------------- helpers
__device__ __forceinline__ uint32_t smem_u32(const void* p) {
    uint32_t a;
    asm("{ .reg .u64 t; cvta.to.shared.u64 t, %1; cvt.u32.u64 %0, t; }" : "=r"(a) : "l"(p));
    return a;
}
#define CP_ASYNC16(smem_addr, gptr) \
    asm volatile("cp.async.cg.shared.global [%0], [%1], 16;" :: "r"(smem_addr), "l"(gptr))
#define CP_COMMIT() asm volatile("cp.async.commit_group;" ::: "memory")
#define CP_WAIT(n)  asm volatile("cp.async.wait_group %0;" :: "n"(n) : "memory")

__device__ __forceinline__ void ldsm_x4(uint32_t& r0, uint32_t& r1, uint32_t& r2, uint32_t& r3,
                                        uint32_t addr) {
    asm volatile("ldmatrix.sync.aligned.m8n8.x4.shared.b16 {%0,%1,%2,%3}, [%4];"
                 : "=r"(r0), "=r"(r1), "=r"(r2), "=r"(r3) : "r"(addr));
}
// fp16-accumulate MMA (full rate)
__device__ __forceinline__ void mma_h(uint32_t& c0, uint32_t& c1,
                                      uint32_t a0, uint32_t a1, uint32_t a2, uint32_t a3,
                                      uint32_t b0, uint32_t b1) {
    asm volatile("mma.sync.aligned.m16n8k16.row.col.f16.f16.f16.f16 "
                 "{%0,%1}, {%2,%3,%4,%5}, {%6,%7}, {%0,%1};"
                 : "+r"(c0), "+r"(c1)
                 : "r"(a0), "r"(a1), "r"(a2), "r"(a3), "r"(b0), "r"(b1));
}

// ---------------- f32 -> f16 conversion (vectorized)
__global__ __launch_bounds__(256) void to_half(const float4* __restrict__ src,
                                               __half2* __restrict__ dst, int n4)
{
    int i = blockIdx.x * blockDim.x + threadIdx.x;
    if (i >= n4) return;
    float4 v = src[i];
    dst[2*i + 0] = __floats2half2_rn(v.x, v.y);
    dst[2*i + 1] = __floats2half2_rn(v.z, v.w);
}

// ---------------- fp16 mma GEMM (fp16 accumulate, promoted to fp32 every 2 k-iters)
// acc[m,n] = sum_d A[m,d]*W[n,d]
// out_h[m,n] = half( bias ? (acc + bias[n]) * mask[m] : acc )
#define BM 128
#define BN 128
#define BK 32
#define LDT_H 40                         // half stride (80B rows; 16B-aligned segments)
#define TILE_H (128*LDT_H)               // 5120 halves = 10240 B
#define STAGE_H (2*TILE_H)               // A + B
#define STAGES 3
#define SMEM_BYTES (STAGES*STAGE_H*2)    // 61440 B
#define LDC 136
#define KITERS (D_MODEL/BK)              // 32
#define PROMOTE 2                        // promote f16->f32 every 2 k-iters (K=64)

extern __shared__ __half sm_h[];

__global__ __launch_bounds__(256, 2)
void gemm_h(const __half* __restrict__ A, const __half* __restrict__ W,
            const float* __restrict__ bias, const float* __restrict__ mask,
            __half* __restrict__ out_h)
{
    const int tid    = threadIdx.x;
    const int warp   = tid >> 5;
    const int lane   = tid & 31;
    const int warp_m = warp & 3;   // 4 row tiles of 32
    const int warp_n = warp >> 2;  // 2 col tiles of 64
    const int m0 = blockIdx.y * BM;
    const int n0 = blockIdx.x * BN;

    const uint32_t sbase = smem_u32(sm_h);

    // cp.async load pattern (unchanged from measured-best config)
    const int r_ld [2] = { (tid + 0)   >> 2, (tid + 256) >> 2 };
    const int c8_ld[2] = { ((tid + 0) & 3) << 3, ((tid + 256) & 3) << 3 };

    auto issue = [&](int ki, int buf) {
        const int k0 = ki * BK;
        const uint32_t sa = sbase + (uint32_t)(buf * STAGE_H) * 2u;
        const uint32_t sb = sa + TILE_H * 2u;
        #pragma unroll
        for (int j = 0; j < 2; j++) {
            int r = r_ld[j], c8 = c8_ld[j];
            uint32_t so = (uint32_t)(r * LDT_H + c8) * 2u;
            CP_ASYNC16(sa + so, A + (size_t)(m0 + r) * D_MODEL + k0 + c8);
            CP_ASYNC16(sb + so, W + (size_t)(n0 + r) * D_MODEL + k0 + c8);
        }
    };

    // ldmatrix per-lane byte offsets within a stage buffer
    // A x4: rows m_tile + (lane&15), col segment +8 halves for lanes>=16
    const uint32_t a_off = (uint32_t)((warp_m * 32 + (lane & 15)) * LDT_H + ((lane >> 4) << 3)) * 2u;
    // B x4: rows n_tile + (lane&7) + 8*(lane>=16), col segment +8 halves for (lane>>3)&1
    const uint32_t b_off = (uint32_t)((warp_n * 64 + (lane & 7) + ((lane >> 4) << 3)) * LDT_H
                                      + (((lane >> 3) & 1) << 3)) * 2u;

    uint32_t hc[2][8][2];                  // f16x2 accumulators
    float    fc[2][8][4];                  // f32 shadow accumulators
    #pragma unroll
    for (int mi = 0; mi < 2; mi++)
        #pragma unroll
        for (int nj = 0; nj < 8; nj++) {
            hc[mi][nj][0] = 0u; hc[mi][nj][1] = 0u;
            fc[mi][nj][0] = 0.f; fc[mi][nj][1] = 0.f; fc[mi][nj][2] = 0.f; fc[mi][nj][3] = 0.f;
        }

    #pragma unroll
    for (int s = 0; s < STAGES - 1; s++) { issue(s, s); CP_COMMIT(); }

    for (int i = 0; i < KITERS; i++) {
        CP_WAIT(1);
        __syncthreads();

        if (i + STAGES - 1 < KITERS) issue(i + STAGES - 1, (i + STAGES - 1) % STAGES);
        CP_COMMIT();

        const uint32_t sa = sbase + (uint32_t)((i % STAGES) * STAGE_H) * 2u;
        const uint32_t sb = sa + TILE_H * 2u;

        #pragma unroll
        for (int kk = 0; kk < BK; kk += 16) {
            uint32_t a[2][4];
            ldsm_x4(a[0][0], a[0][1], a[0][2], a[0][3], sa + a_off + kk * 2);
            ldsm_x4(a[1][0], a[1][1], a[1][2], a[1][3], sa + a_off + (16 * LDT_H) * 2 + kk * 2);
            #pragma unroll
            for (int p = 0; p < 4; p++) {      // each x4 serves two n-octets
                uint32_t b0, b1, b2, b3;
                ldsm_x4(b0, b1, b2, b3, sb + b_off + (p * 16 * LDT_H) * 2 + kk * 2);
                int nj = p * 2;
                mma_h(hc[0][nj+0][0], hc[0][nj+0][1], a[0][0], a[0][1], a[0][2], a[0][3], b0, b1);
                mma_h(hc[1][nj+0][0], hc[1][nj+0][1], a[1][0], a[1][1], a[1][2], a[1][3], b0, b1);
                mma_h(hc[0][nj+1][0], hc[0][nj+1][1], a[0][0], a[0][1], a[0][2], a[0][3], b2, b3);
                mma_h(hc[1][nj+1][0], hc[1][nj+1][1], a[1][0], a[1][1], a[1][2], a[1][3], b2, b3);
            }
        }

        if ((i & (PROMOTE - 1)) == (PROMOTE - 1)) {
            #pragma unroll
            for (int mi = 0; mi < 2; mi++)
                #pragma unroll
                for (int nj = 0; nj < 8; nj++) {
                    float2 f0 = __half22float2(*(__half2*)&hc[mi][nj][0]);
                    float2 f1 = __half22float2(*(__half2*)&hc[mi][nj][1]);
                    fc[mi][nj][0] += f0.x; fc[mi][nj][1] += f0.y;
                    fc[mi][nj][2] += f1.x; fc[mi][nj][3] += f1.y;
                    hc[mi][nj][0] = 0u;   hc[mi][nj][1] = 0u;
                }
        }
    }
    __syncthreads();

    // Epilogue: two 64-row stages through smem; fuse (optional) bias+mask; half output.
    // f32 mma layout: g = lane>>2 (row), s = lane&3 (col pair): (g,2s),(g,2s+1),(g+8,2s),(g+8,2s+1)
    const int g = lane >> 2;
    const int s2 = (lane & 3) << 1;
    float* Cs = (float*)sm_h;
    #pragma unroll
    for (int stage = 0; stage < 2; stage++) {
        if ((warp_m >> 1) == stage) {
            int rbase = (warp_m & 1) * 32;
            #pragma unroll
            for (int mi = 0; mi < 2; mi++)
                #pragma unroll
                for (int nj = 0; nj < 8; nj++) {
                    int rr = rbase + mi * 16 + g;
                    int cc = warp_n * 64 + nj * 8 + s2;
                    *(float2*)(Cs + rr * LDC + cc)       = make_float2(fc[mi][nj][0], fc[mi][nj][1]);
                    *(float2*)(Cs + (rr + 8) * LDC + cc) = make_float2(fc[mi][nj][2], fc[mi][nj][3]);
                }
        }
        __syncthreads();
        #pragma unroll
        for (int it = 0; it < 8; it++) {
            int idx = (tid + it * 256) << 2;   // 0..8188
            int rr = idx >> 7;                 // 0..63
            int cc = idx & 127;
            int gm = m0 + stage * 64 + rr;
            int gn = n0 + cc;
            float4 v = *(const float4*)(Cs + rr * LDC + cc);
            if (bias) {
                float4 bb = *(const float4*)(bias + gn);
                float mv = mask[gm];
                v.x = (v.x + bb.x) * mv;
                v.y = (v.y + bb.y) * mv;
                v.z = (v.z + bb.z) * mv;
                v.w = (v.w + bb.w) * mv;
            }
            __half2* dst = (__half2*)(out_h + (size_t)gm * D_MODEL + gn);
            dst[0] = __floats2half2_rn(v.x, v.y);
            dst[1] = __floats2half2_rn(v.z, v.w);
        }
        __syncthreads();
    }
}

// ---------------- Decay scan on v (half), chunked 3-pass, 4 lanes/thread
__device__ __forceinline__ float get_decay(const float* dp) {
    return 1.0f / (1.0f + expf(-dp[0]));
}

__global__ __launch_bounds__(256) void scan_pass1(const float* __restrict__ dp)
{
    float decay = get_decay(dp);
    int c = blockIdx.x;
    int b = blockIdx.y;
    int e4 = threadIdx.x << 2;
    const __half* v = g_xh + ((size_t)(b * SEQ + c * CHUNK)) * D_MODEL + e4;
    float4 h = make_float4(0.f, 0.f, 0.f, 0.f);
    #pragma unroll 8
    for (int s = 0; s < CHUNK; s++) {
        uint2 raw = *(const uint2*)(v + (size_t)s * D_MODEL);
        float2 f0 = __half22float2(*(__half2*)&raw.x);
        float2 f1 = __half22float2(*(__half2*)&raw.y);
        h.x = fmaf(decay, h.x, f0.x);
        h.y = fmaf(decay, h.y, f0.y);
        h.z = fmaf(decay, h.z, f1.x);
        h.w = fmaf(decay, h.w, f1.y);
    }
    *(float4*)(g_C + ((size_t)b * NCHUNK + c) * D_MODEL + e4) = h;
}

__global__ __launch_bounds__(256) void scan_pass2(const float* __restrict__ dp)
{
    float decay = get_decay(dp);
    float dpow = decay;
    #pragma unroll
    for (int i = 0; i < 5; i++) dpow *= dpow;  // decay^32 (CHUNK=32)
    int idx = blockIdx.x * 256 + threadIdx.x;  // 0..4095
    int b = idx >> 10;
    int e = idx & 1023;
    float he = 0.0f;
    #pragma unroll 8
    for (int c = 0; c < NCHUNK; c++) {
        size_t off = ((size_t)b * NCHUNK + c) * D_MODEL + e;
        g_cin[off] = he;
        he = fmaf(dpow, he, g_C[off]);
    }
}

__global__ __launch_bounds__(256) void scan_pass3(const float* __restrict__ dp,
                                                  const float* __restrict__ bias,
                                                  float* __restrict__ dst)
{
    float decay = get_decay(dp);
    int c = blockIdx.x;
    int b = blockIdx.y;
    int e4 = threadIdx.x << 2;
    size_t base = ((size_t)(b * SEQ + c * CHUNK)) * D_MODEL + e4;
    const __half* v = g_xh + base;
    float*        o = dst  + base;
    float4 bf = *(const float4*)(bias + e4);
    float4 acc = *(const float4*)(g_cin + ((size_t)b * NCHUNK + c) * D_MODEL + e4);
    #pragma unroll 8
    for (int s = 0; s < CHUNK; s++) {
        uint2 raw = *(const uint2*)(v + (size_t)s * D_MODEL);
        float2 f0 = __half22float2(*(__half2*)&raw.x);
        float2 f1 = __half22float2(*(__half2*)&raw.y);
        acc.x = fmaf(decay, acc.x, f0.x);
        acc.y = fmaf(decay, acc.y, f0.y);
        acc.z = fmaf(decay, acc.z, f1.x);
        acc.w = fmaf(decay, acc.w, f1.y);
        float4 w;
        w.x = acc.x + bf.x;
        w.y = acc.y + bf.y;
        w.z = acc.z + bf.z;
        w.w = acc.w + bf.w;
        *(float4*)(o + (size_t)s * D_MODEL) = w;
    }
}

// ---------------- launch
extern "C" void kernel_launch(void* const* d_in, const int* in_sizes, int n_in,
                              void* d_out, int out_size)
{
    const float* x     = (const float*)d_in[0];
    const float* mask  = (const float*)d_in[1];
    const float* W_up  = (const float*)d_in[2];
    const float* b_up  = (const float*)d_in[3];
    const float* W_f   = (const float*)d_in[4];
    const float* b_f   = (const float*)d_in[5];
    const float* dp    = (const float*)d_in[6];
    float* out = (float*)d_out;

    __half *xh, *uh, *w1h, *w2h;
    cudaGetSymbolAddress((void**)&xh,  g_xh);
    cudaGetSymbolAddress((void**)&uh,  g_uh);
    cudaGetSymbolAddress((void**)&w1h, g_w1h);
    cudaGetSymbolAddress((void**)&w2h, g_w2h);

    cudaFuncSetAttribute(gemm_h, cudaFuncAttributeMaxDynamicSharedMemorySize, SMEM_BYTES);

    dim3 ggrid(D_MODEL / BN, M_TOTAL / BM);   // (8, 128)

    // convert inputs to fp16
    to_half<<<NX / 4 / 256, 256>>>((const float4*)x,    (__half2*)xh,  NX / 4);
    to_half<<<D2 / 4 / 256, 256>>>((const float4*)W_up, (__half2*)w1h, D2 / 4);
    to_half<<<D2 / 4 / 256, 256>>>((const float4*)W_f,  (__half2*)w2h, D2 / 4);

    // u = half((x @ W_up^T + b_up) * mask)
    gemm_h<<<ggrid, 256, SMEM_BYTES>>>(xh, w1h, b_up, mask, uh);

    // v = half(u @ W_f^T)   (x dead -> reuse g_xh as v; scan commutes with linear map)
    gemm_h<<<ggrid, 256, SMEM_BYTES>>>(uh, w2h, nullptr, nullptr, xh);

    // out = scan(v) + b_f
    scan_pass1<<<dim3(NCHUNK, BATCH), 256>>>(dp);
    scan_pass2<<<16, 256>>>(dp);
    scan_pass3<<<dim3(NCHUNK, BATCH), 256>>>(dp, b_f, out);
}

// round 16
// speedup vs baseline: 1.2530x; 1.2530x over previous
#include <cuda_runtime.h>
#include <cuda_fp16.h>
#include <cstdint>

#define D_MODEL 1024
#define BATCH   4
#define SEQ     4096
#define M_TOTAL (BATCH*SEQ)
#define NX      (M_TOTAL*D_MODEL)      // 16M
#define D2      (D_MODEL*D_MODEL)      // 1M

#define CHUNK  32
#define NCHUNK (SEQ/CHUNK)   // 128

// ---------------- scratch (__device__ globals, allocation-free rule)
__device__ __half g_xh[NX];            // x (half); reused as v (half) after GEMM2
__device__ __half g_uh[NX];            // u (half) after GEMM1
__device__ __half g_w1h[D2];
__device__ __half g_w2h[D2];
__device__ float  g_C  [BATCH*NCHUNK*D_MODEL];
__device__ float  g_cin[BATCH*NCHUNK*D_MODEL];

// ---------------- helpers
__device__ __forceinline__ uint32_t smem_u32(const void* p) {
    uint32_t a;
    asm("{ .reg .u64 t; cvta.to.shared.u64 t, %1; cvt.u32.u64 %0, t; }" : "=r"(a) : "l"(p));
    return a;
}
#define CP_ASYNC16(smem_addr, gptr) \
    asm volatile("cp.async.cg.shared.global [%0], [%1], 16;" :: "r"(smem_addr), "l"(gptr))
#define CP_COMMIT() asm volatile("cp.async.commit_group;" ::: "memory")
#define CP_WAIT0()  asm volatile("cp.async.wait_group 0;" ::: "memory")

__device__ __forceinline__ void ldsm_x4(uint32_t& r0, uint32_t& r1, uint32_t& r2, uint32_t& r3,
                                        uint32_t addr) {
    asm volatile("ldmatrix.sync.aligned.m8n8.x4.shared.b16 {%0,%1,%2,%3}, [%4];"
                 : "=r"(r0), "=r"(r1), "=r"(r2), "=r"(r3) : "r"(addr));
}
// fp32-accumulate fp16 MMA
__device__ __forceinline__ void mma_f32(float* c,
                                        uint32_t a0, uint32_t a1, uint32_t a2, uint32_t a3,
                                        uint32_t b0, uint32_t b1) {
    asm volatile("mma.sync.aligned.m16n8k16.row.col.f32.f16.f16.f32 "
                 "{%0,%1,%2,%3}, {%4,%5,%6,%7}, {%8,%9}, {%0,%1,%2,%3};"
                 : "+f"(c[0]), "+f"(c[1]), "+f"(c[2]), "+f"(c[3])
                 : "r"(a0), "r"(a1), "r"(a2), "r"(a3), "r"(b0), "r"(b1));
}

// ---------------- f32 -> f16 conversion (vectorized)
__global__ __launch_bounds__(256) void to_half(const float4* __restrict__ src,
                                               __half2* __restrict__ dst, int n4)
{
    int i = blockIdx.x * blockDim.x + threadIdx.x;
    if (i >= n4) return;
    float4 v = src[i];
    dst[2*i + 0] = __floats2half2_rn(v.x, v.y);
    dst[2*i + 1] = __floats2half2_rn(v.z, v.w);
}

// ---------------- fp16 mma GEMM (f32 acc), 2-stage cp.async, kk-pipelined fragments
// acc[m,n] = sum_d A[m,d]*W[n,d]
// out_h[m,n] = half( bias ? (acc + bias[n]) * mask[m] : acc )
#define BM 128
#define BN 128
#define BK 64
#define LDT_H 72                         // half stride (144B rows; ldsm bank-conflict-free)
#define TILE_H (128*LDT_H)               // 9216 halves = 18432 B
#define STAGE_H (2*TILE_H)               // A + B = 36864 B
#define STAGES 2
#define SMEM_BYTES (STAGES*STAGE_H*2)    // 73728 B
#define LDC 136
#define KITERS (D_MODEL/BK)              // 16

extern __shared__ __half sm_h[];

__global__ __launch_bounds__(256, 2)
void gemm_h(const __half* __restrict__ A, const __half* __restrict__ W,
            const float* __restrict__ bias, const float* __restrict__ mask,
            __half* __restrict__ out_h)
{
    const int tid    = threadIdx.x;
    const int warp   = tid >> 5;
    const int lane   = tid & 31;
    const int warp_m = warp & 3;   // 4 row tiles of 32
    const int warp_n = warp >> 2;  // 2 col tiles of 64
    const int m0 = blockIdx.y * BM;
    const int n0 = blockIdx.x * BN;

    const uint32_t sbase = smem_u32(sm_h);

    // cp.async: per matrix 128 rows x 64 halves = 1024 16B-chunks; 4 per thread.
    auto issue = [&](int ki, int buf) {
        const int k0 = ki * BK;
        const uint32_t sa = sbase + (uint32_t)(buf * STAGE_H) * 2u;
        const uint32_t sb = sa + TILE_H * 2u;
        #pragma unroll
        for (int j = 0; j < 4; j++) {
            int idx = tid + j * 256;          // 0..1023
            int r   = idx >> 3;               // row 0..127
            int c8  = (idx & 7) << 3;         // half col 0,8,...,56
            uint32_t so = (uint32_t)(r * LDT_H + c8) * 2u;
            CP_ASYNC16(sa + so, A + (size_t)(m0 + r) * D_MODEL + k0 + c8);
            CP_ASYNC16(sb + so, W + (size_t)(n0 + r) * D_MODEL + k0 + c8);
        }
    };

    // ldmatrix per-lane byte offsets (validated in R15)
    const uint32_t a_off = (uint32_t)((warp_m * 32 + (lane & 15)) * LDT_H + ((lane >> 4) << 3)) * 2u;
    const uint32_t b_off = (uint32_t)((warp_n * 64 + (lane & 7) + ((lane >> 4) << 3)) * LDT_H
                                      + (((lane >> 3) & 1) << 3)) * 2u;

    float fc[2][8][4];                     // f32 accumulators (m16n8 frags: 2m x 8n)
    #pragma unroll
    for (int mi = 0; mi < 2; mi++)
        #pragma unroll
        for (int nj = 0; nj < 8; nj++)
            #pragma unroll
            for (int q = 0; q < 4; q++) fc[mi][nj][q] = 0.f;

    uint32_t af[2][2][4];                  // [buf][m-frag][4]
    uint32_t bf[2][4][4];                  // [buf][n-octet-pair][4]

    issue(0, 0); CP_COMMIT();

    for (int i = 0; i < KITERS; i++) {
        CP_WAIT0();                        // stage i data resident
        __syncthreads();                   // + all warps done with the other buffer

        if (i + 1 < KITERS) { issue(i + 1, (i + 1) & 1); CP_COMMIT(); }

        const uint32_t sa = sbase + (uint32_t)((i & 1) * STAGE_H) * 2u;
        const uint32_t sb = sa + TILE_H * 2u;

        // preload kk=0 fragments
        ldsm_x4(af[0][0][0], af[0][0][1], af[0][0][2], af[0][0][3], sa + a_off);
        ldsm_x4(af[0][1][0], af[0][1][1], af[0][1][2], af[0][1][3], sa + a_off + (16 * LDT_H) * 2);
        #pragma unroll
        for (int p = 0; p < 4; p++)
            ldsm_x4(bf[0][p][0], bf[0][p][1], bf[0][p][2], bf[0][p][3],
                    sb + b_off + (p * 16 * LDT_H) * 2);

        #pragma unroll
        for (int k = 0; k < BK / 16; k++) {
            const int cur = k & 1, nxt = cur ^ 1;
            if (k + 1 < BK / 16) {
                const uint32_t ko = (uint32_t)(k + 1) * 32u;   // 16 halves = 32 B
                ldsm_x4(af[nxt][0][0], af[nxt][0][1], af[nxt][0][2], af[nxt][0][3],
                        sa + a_off + ko);
                ldsm_x4(af[nxt][1][0], af[nxt][1][1], af[nxt][1][2], af[nxt][1][3],
                        sa + a_off + (16 * LDT_H) * 2 + ko);
                #pragma unroll
                for (int p = 0; p < 4; p++)
                    ldsm_x4(bf[nxt][p][0], bf[nxt][p][1], bf[nxt][p][2], bf[nxt][p][3],
                            sb + b_off + (p * 16 * LDT_H) * 2 + ko);
            }
            #pragma unroll
            for (int p = 0; p < 4; p++) {
                int nj = p * 2;
                mma_f32(fc[0][nj+0], af[cur][0][0], af[cur][0][1], af[cur][0][2], af[cur][0][3],
                        bf[cur][p][0], bf[cur][p][1]);
                mma_f32(fc[1][nj+0], af[cur][1][0], af[cur][1][1], af[cur][1][2], af[cur][1][3],
                        bf[cur][p][0], bf[cur][p][1]);
                mma_f32(fc[0][nj+1], af[cur][0][0], af[cur][0][1], af[cur][0][2], af[cur][0][3],
                        bf[cur][p][2], bf[cur][p][3]);
                mma_f32(fc[1][nj+1], af[cur][1][0], af[cur][1][1], af[cur][1][2], af[cur][1][3],
                        bf[cur][p][2], bf[cur][p][3]);
            }
        }
    }
    __syncthreads();

    // Epilogue (R15-validated layout): two 64-row stages through smem; fuse bias+mask; half out.
    const int g  = lane >> 2;
    const int s2 = (lane & 3) << 1;
    float* Cs = (float*)sm_h;
    #pragma unroll
    for (int stage = 0; stage < 2; stage++) {
        if ((warp_m >> 1) == stage) {
            int rbase = (warp_m & 1) * 32;
            #pragma unroll
            for (int mi = 0; mi < 2; mi++)
                #pragma unroll
                for (int nj = 0; nj < 8; nj++) {
                    int rr = rbase + mi * 16 + g;
                    int cc = warp_n * 64 + nj * 8 + s2;
                    *(float2*)(Cs + rr * LDC + cc)       = make_float2(fc[mi][nj][0], fc[mi][nj][1]);
                    *(float2*)(Cs + (rr + 8) * LDC + cc) = make_float2(fc[mi][nj][2], fc[mi][nj][3]);
                }
        }
        __syncthreads();
        #pragma unroll
        for (int it = 0; it < 8; it++) {
            int idx = (tid + it * 256) << 2;   // 0..8188
            int rr = idx >> 7;                 // 0..63
            int cc = idx & 127;
            int gm = m0 + stage * 64 + rr;
            int gn = n0 + cc;
            float4 v = *(const float4*)(Cs + rr * LDC + cc);
            if (bias) {
                float4 bb = *(const float4*)(bias + gn);
                float mv = mask[gm];
                v.x = (v.x + bb.x) * mv;
                v.y = (v.y + bb.y) * mv;
                v.z = (v.z + bb.z) * mv;
                v.w = (v.w + bb.w) * mv;
            }
            __half2* dst = (__half2*)(out_h + (size_t)gm * D_MODEL + gn);
            dst[0] = __floats2half2_rn(v.x, v.y);
            dst[1] = __floats2half2_rn(v.z, v.w);
        }
        __syncthreads();
    }
}

// ---------------- Decay scan on v (half), chunked 3-pass, 4 lanes/thread
__device__ __forceinline__ float get_decay(const float* dp) {
    return 1.0f / (1.0f + expf(-dp[0]));
}

__global__ __launch_bounds__(256) void scan_pass1(const float* __restrict__ dp)
{
    float decay = get_decay(dp);
    int c = blockIdx.x;
    int b = blockIdx.y;
    int e4 = threadIdx.x << 2;
    const __half* v = g_xh + ((size_t)(b * SEQ + c * CHUNK)) * D_MODEL + e4;
    float4 h = make_float4(0.f, 0.f, 0.f, 0.f);
    #pragma unroll 8
    for (int s = 0; s < CHUNK; s++) {
        uint2 raw = *(const uint2*)(v + (size_t)s * D_MODEL);
        float2 f0 = __half22float2(*(__half2*)&raw.x);
        float2 f1 = __half22float2(*(__half2*)&raw.y);
        h.x = fmaf(decay, h.x, f0.x);
        h.y = fmaf(decay, h.y, f0.y);
        h.z = fmaf(decay, h.z, f1.x);
        h.w = fmaf(decay, h.w, f1.y);
    }
    *(float4*)(g_C + ((size_t)b * NCHUNK + c) * D_MODEL + e4) = h;
}

__global__ __launch_bounds__(256) void scan_pass2(const float* __restrict__ dp)
{
    float decay = get_decay(dp);
    float dpow = decay;
    #pragma unroll
    for (int i = 0; i < 5; i++) dpow *= dpow;  // decay^32 (CHUNK=32)
    int idx = blockIdx.x * 256 + threadIdx.x;  // 0..4095
    int b = idx >> 10;
    int e = idx & 1023;
    float he = 0.0f;
    #pragma unroll 8
    for (int c = 0; c < NCHUNK; c++) {
        size_t off = ((size_t)b * NCHUNK + c) * D_MODEL + e;
        g_cin[off] = he;
        he = fmaf(dpow, he, g_C[off]);
    }
}

__global__ __launch_bounds__(256) void scan_pass3(const float* __restrict__ dp,
                                                  const float* __restrict__ bias,
                                                  float* __restrict__ dst)
{
    float decay = get_decay(dp);
    int c = blockIdx.x;
    int b = blockIdx.y;
    int e4 = threadIdx.x << 2;
    size_t base = ((size_t)(b * SEQ + c * CHUNK)) * D_MODEL + e4;
    const __half* v = g_xh + base;
    float*        o = dst  + base;
    float4 bf = *(const float4*)(bias + e4);
    float4 acc = *(const float4*)(g_cin + ((size_t)b * NCHUNK + c) * D_MODEL + e4);
    #pragma unroll 8
    for (int s = 0; s < CHUNK; s++) {
        uint2 raw = *(const uint2*)(v + (size_t)s * D_MODEL);
        float2 f0 = __half22float2(*(__half2*)&raw.x);
        float2 f1 = __half22float2(*(__half2*)&raw.y);
        acc.x = fmaf(decay, acc.x, f0.x);
        acc.y = fmaf(decay, acc.y, f0.y);
        acc.z = fmaf(decay, acc.z, f1.x);
        acc.w = fmaf(decay, acc.w, f1.y);
        float4 w;
        w.x = acc.x + bf.x;
        w.y = acc.y + bf.y;
        w.z = acc.z + bf.z;
        w.w = acc.w + bf.w;
        *(float4*)(o + (size_t)s * D_MODEL) = w;
    }
}

// ---------------- launch
extern "C" void kernel_launch(void* const* d_in, const int* in_sizes, int n_in,
                              void* d_out, int out_size)
{
    const float* x     = (const float*)d_in[0];
    const float* mask  = (const float*)d_in[1];
    const float* W_up  = (const float*)d_in[2];
    const float* b_up  = (const float*)d_in[3];
    const float* W_f   = (const float*)d_in[4];
    const float* b_f   = (const float*)d_in[5];
    const float* dp    = (const float*)d_in[6];
    float* out = (float*)d_out;

    __half *xh, *uh, *w1h, *w2h;
    cudaGetSymbolAddress((void**)&xh,  g_xh);
    cudaGetSymbolAddress((void**)&uh,  g_uh);
    cudaGetSymbolAddress((void**)&w1h, g_w1h);
    cudaGetSymbolAddress((void**)&w2h, g_w2h);

    cudaFuncSetAttribute(gemm_h, cudaFuncAttributeMaxDynamicSharedMemorySize, SMEM_BYTES);

    dim3 ggrid(D_MODEL / BN, M_TOTAL / BM);   // (8, 128)

    // convert inputs to fp16
    to_half<<<NX / 4 / 256, 256>>>((const float4*)x,    (__half2*)xh,  NX / 4);
    to_half<<<D2 / 4 / 256, 256>>>((const float4*)W_up, (__half2*)w1h, D2 / 4);
    to_half<<<D2 / 4 / 256, 256>>>((const float4*)W_f,  (__half2*)w2h, D2 / 4);

    // u = half((x @ W_up^T + b_up) * mask)
    gemm_h<<<ggrid, 256, SMEM_BYTES>>>(xh, w1h, b_up, mask, uh);

    // v = half(u @ W_f^T)   (x dead -> reuse g_xh as v; scan commutes with linear map)
    gemm_h<<<ggrid, 256, SMEM_BYTES>>>(uh, w2h, nullptr, nullptr, xh);

    // out = scan(v) + b_f
    scan_pass1<<<dim3(NCHUNK, BATCH), 256>>>(dp);
    scan_pass2<<<16, 256>>>(dp);
    scan_pass3<<<dim3(NCHUNK, BATCH), 256>>>(dp, b_f, out);
}

// round 17
// speedup vs baseline: 1.2659x; 1.0104x over previous
#include <cuda_runtime.h>
#include <cuda_fp16.h>
#include <cstdint>

#define D_MODEL 1024
#define BATCH   4
#define SEQ     4096
#define M_TOTAL (BATCH*SEQ)
#define NX      (M_TOTAL*D_MODEL)      // 16M
#define D2      (D_MODEL*D_MODEL)      // 1M

#define CHUNK  32
#define NCHUNK (SEQ/CHUNK)   // 128

// ---------------- scratch (__device__ globals, allocation-free rule)
__device__ __half g_xh[NX];            // x (half); reused as v (half) after GEMM2
__device__ __half g_uh[NX];            // u (half) after GEMM1
__device__ __half g_w1h[D2];
__device__ __half g_w2h[D2];
__device__ float  g_C  [BATCH*NCHUNK*D_MODEL];
__device__ float  g_cin[BATCH*NCHUNK*D_MODEL];

// ---------------- helpers
__device__ __forceinline__ uint32_t smem_u32(const void* p) {
    uint32_t a;
    asm("{ .reg .u64 t; cvta.to.shared.u64 t, %1; cvt.u32.u64 %0, t; }" : "=r"(a) : "l"(p));
    return a;
}
#define CP_ASYNC16(smem_addr, gptr) \
    asm volatile("cp.async.cg.shared.global [%0], [%1], 16;" :: "r"(smem_addr), "l"(gptr))
#define CP_COMMIT() asm volatile("cp.async.commit_group;" ::: "memory")
#define CP_WAIT(n)  asm volatile("cp.async.wait_group %0;" :: "n"(n) : "memory")

__device__ __forceinline__ void ldsm_x4(uint32_t& r0, uint32_t& r1, uint32_t& r2, uint32_t& r3,
                                        uint32_t addr) {
    asm volatile("ldmatrix.sync.aligned.m8n8.x4.shared.b16 {%0,%1,%2,%3}, [%4];"
                 : "=r"(r0), "=r"(r1), "=r"(r2), "=r"(r3) : "r"(addr));
}
// fp32-accumulate fp16 MMA
__device__ __forceinline__ void mma_f32(float* c,
                                        uint32_t a0, uint32_t a1, uint32_t a2, uint32_t a3,
                                        uint32_t b0, uint32_t b1) {
    asm volatile("mma.sync.aligned.m16n8k16.row.col.f32.f16.f16.f32 "
                 "{%0,%1,%2,%3}, {%4,%5,%6,%7}, {%8,%9}, {%0,%1,%2,%3};"
                 : "+f"(c[0]), "+f"(c[1]), "+f"(c[2]), "+f"(c[3])
                 : "r"(a0), "r"(a1), "r"(a2), "r"(a3), "r"(b0), "r"(b1));
}

__device__ __forceinline__ float get_decay(const float* dp) {
    return 1.0f / (1.0f + expf(-dp[0]));
}

// ---------------- f32 -> f16 conversion (vectorized)
__global__ __launch_bounds__(256) void to_half(const float4* __restrict__ src,
                                               __half2* __restrict__ dst, int n4)
{
    int i = blockIdx.x * blockDim.x + threadIdx.x;
    if (i >= n4) return;
    float4 v = src[i];
    dst[2*i + 0] = __floats2half2_rn(v.x, v.y);
    dst[2*i + 1] = __floats2half2_rn(v.z, v.w);
}

// ---------------- fp16 mma GEMM (f32 acc), 3-stage cp.async, kk-pipelined fragments
// acc[m,n] = sum_d A[m,d]*W[n,d]
// out_h[m,n] = half( bias ? (acc + bias[n]) * mask[m] : acc )
// If dp != 0 (GEMM2): epilogue also emits 32-row decay-weighted chunk sums into g_C.
#define BM 128
#define BN 128
#define BK 64
#define LDT_H 72                         // half stride (144B rows; ldsm bank-conflict-free)
#define TILE_H (128*LDT_H)               // 9216 halves = 18432 B
#define STAGE_H (2*TILE_H)               // A + B = 36864 B
#define STAGES 3
#define SMEM_BYTES (STAGES*STAGE_H*2)    // 110592 B
#define LDC 136
#define KITERS (D_MODEL/BK)              // 16

extern __shared__ __half sm_h[];

__global__ __launch_bounds__(256, 2)
void gemm_h(const __half* __restrict__ A, const __half* __restrict__ W,
            const float* __restrict__ bias, const float* __restrict__ mask,
            __half* __restrict__ out_h, const float* __restrict__ dp)
{
    const int tid    = threadIdx.x;
    const int warp   = tid >> 5;
    const int lane   = tid & 31;
    const int warp_m = warp & 3;   // 4 row tiles of 32
    const int warp_n = warp >> 2;  // 2 col tiles of 64
    const int m0 = blockIdx.y * BM;
    const int n0 = blockIdx.x * BN;

    const uint32_t sbase = smem_u32(sm_h);

    // cp.async: per matrix 128 rows x 64 halves = 1024 16B-chunks; 4 per thread.
    auto issue = [&](int ki, int buf) {
        const int k0 = ki * BK;
        const uint32_t sa = sbase + (uint32_t)(buf * STAGE_H) * 2u;
        const uint32_t sb = sa + TILE_H * 2u;
        #pragma unroll
        for (int j = 0; j < 4; j++) {
            int idx = tid + j * 256;          // 0..1023
            int r   = idx >> 3;               // row 0..127
            int c8  = (idx & 7) << 3;         // half col 0,8,...,56
            uint32_t so = (uint32_t)(r * LDT_H + c8) * 2u;
            CP_ASYNC16(sa + so, A + (size_t)(m0 + r) * D_MODEL + k0 + c8);
            CP_ASYNC16(sb + so, W + (size_t)(n0 + r) * D_MODEL + k0 + c8);
        }
    };

    // ldmatrix per-lane byte offsets (validated in R15/R16)
    const uint32_t a_off = (uint32_t)((warp_m * 32 + (lane & 15)) * LDT_H + ((lane >> 4) << 3)) * 2u;
    const uint32_t b_off = (uint32_t)((warp_n * 64 + (lane & 7) + ((lane >> 4) << 3)) * LDT_H
                                      + (((lane >> 3) & 1) << 3)) * 2u;

    float fc[2][8][4];                     // f32 accumulators (m16n8 frags: 2m x 8n)
    #pragma unroll
    for (int mi = 0; mi < 2; mi++)
        #pragma unroll
        for (int nj = 0; nj < 8; nj++)
            #pragma unroll
            for (int q = 0; q < 4; q++) fc[mi][nj][q] = 0.f;

    uint32_t af[2][2][4];                  // [buf][m-frag][4]
    uint32_t bf[2][4][4];                  // [buf][n-octet-pair][4]

    issue(0, 0); CP_COMMIT();
    issue(1, 1); CP_COMMIT();

    for (int i = 0; i < KITERS; i++) {
        CP_WAIT(1);                        // stage i resident (stage i+1 may be in flight)
        __syncthreads();                   // + all warps done with buf (i+2)%3 (iter i-1)

        if (i + 2 < KITERS) { issue(i + 2, (i + 2) % 3); CP_COMMIT(); }

        const uint32_t sa = sbase + (uint32_t)((i % 3) * STAGE_H) * 2u;
        const uint32_t sb = sa + TILE_H * 2u;

        // preload kk=0 fragments
        ldsm_x4(af[0][0][0], af[0][0][1], af[0][0][2], af[0][0][3], sa + a_off);
        ldsm_x4(af[0][1][0], af[0][1][1], af[0][1][2], af[0][1][3], sa + a_off + (16 * LDT_H) * 2);
        #pragma unroll
        for (int p = 0; p < 4; p++)
            ldsm_x4(bf[0][p][0], bf[0][p][1], bf[0][p][2], bf[0][p][3],
                    sb + b_off + (p * 16 * LDT_H) * 2);

        #pragma unroll
        for (int k = 0; k < BK / 16; k++) {
            const int cur = k & 1, nxt = cur ^ 1;
            if (k + 1 < BK / 16) {
                const uint32_t ko = (uint32_t)(k + 1) * 32u;   // 16 halves = 32 B
                ldsm_x4(af[nxt][0][0], af[nxt][0][1], af[nxt][0][2], af[nxt][0][3],
                        sa + a_off + ko);
                ldsm_x4(af[nxt][1][0], af[nxt][1][1], af[nxt][1][2], af[nxt][1][3],
                        sa + a_off + (16 * LDT_H) * 2 + ko);
                #pragma unroll
                for (int p = 0; p < 4; p++)
                    ldsm_x4(bf[nxt][p][0], bf[nxt][p][1], bf[nxt][p][2], bf[nxt][p][3],
                            sb + b_off + (p * 16 * LDT_H) * 2 + ko);
            }
            #pragma unroll
            for (int p = 0; p < 4; p++) {
                int nj = p * 2;
                mma_f32(fc[0][nj+0], af[cur][0][0], af[cur][0][1], af[cur][0][2], af[cur][0][3],
                        bf[cur][p][0], bf[cur][p][1]);
                mma_f32(fc[1][nj+0], af[cur][1][0], af[cur][1][1], af[cur][1][2], af[cur][1][3],
                        bf[cur][p][0], bf[cur][p][1]);
                mma_f32(fc[0][nj+1], af[cur][0][0], af[cur][0][1], af[cur][0][2], af[cur][0][3],
                        bf[cur][p][2], bf[cur][p][3]);
                mma_f32(fc[1][nj+1], af[cur][1][0], af[cur][1][1], af[cur][1][2], af[cur][1][3],
                        bf[cur][p][2], bf[cur][p][3]);
            }
        }
    }
    __syncthreads();

    const float decay = dp ? get_decay(dp) : 0.0f;

    // Epilogue: two 64-row stages through smem; fuse bias+mask (GEMM1) or
    // 32-row decayed chunk sums into g_C (GEMM2); half output.
    const int g  = lane >> 2;
    const int s2 = (lane & 3) << 1;
    float* Cs = (float*)sm_h;
    #pragma unroll
    for (int stage = 0; stage < 2; stage++) {
        if ((warp_m >> 1) == stage) {
            int rbase = (warp_m & 1) * 32;
            #pragma unroll
            for (int mi = 0; mi < 2; mi++)
                #pragma unroll
                for (int nj = 0; nj < 8; nj++) {
                    int rr = rbase + mi * 16 + g;
                    int cc = warp_n * 64 + nj * 8 + s2;
                    *(float2*)(Cs + rr * LDC + cc)       = make_float2(fc[mi][nj][0], fc[mi][nj][1]);
                    *(float2*)(Cs + (rr + 8) * LDC + cc) = make_float2(fc[mi][nj][2], fc[mi][nj][3]);
                }
        }
        __syncthreads();
        #pragma unroll
        for (int it = 0; it < 8; it++) {
            int idx = (tid + it * 256) << 2;   // 0..8188
            int rr = idx >> 7;                 // 0..63
            int cc = idx & 127;
            int gm = m0 + stage * 64 + rr;
            int gn = n0 + cc;
            float4 v = *(const float4*)(Cs + rr * LDC + cc);
            if (bias) {
                float4 bb = *(const float4*)(bias + gn);
                float mv = mask[gm];
                v.x = (v.x + bb.x) * mv;
                v.y = (v.y + bb.y) * mv;
                v.z = (v.z + bb.z) * mv;
                v.w = (v.w + bb.w) * mv;
            }
            __half2* dst = (__half2*)(out_h + (size_t)gm * D_MODEL + gn);
            dst[0] = __floats2half2_rn(v.x, v.y);
            dst[1] = __floats2half2_rn(v.z, v.w);
        }
        // Fused scan_pass1 (GEMM2 only): per-column 32-row decayed sums.
        // This 64-row stage covers chunks (blockIdx.y*4 + stage*2 + {0,1}).
        if (dp && tid < 128) {
            float acc0 = 0.f, acc1 = 0.f;
            #pragma unroll 8
            for (int r = 0; r < 32; r++)
                acc0 = fmaf(decay, acc0, Cs[r * LDC + tid]);
            #pragma unroll 8
            for (int r = 32; r < 64; r++)
                acc1 = fmaf(decay, acc1, Cs[r * LDC + tid]);
            const int b      = m0 >> 12;                       // /4096
            const int cLocal = ((blockIdx.y & 31) << 2) + stage * 2;
            const int e      = n0 + tid;
            g_C[((size_t)b * NCHUNK + cLocal    ) * D_MODEL + e] = acc0;
            g_C[((size_t)b * NCHUNK + cLocal + 1) * D_MODEL + e] = acc1;
        }
        __syncthreads();
    }
}

// ---------------- Decay scan passes 2/3 (pass1 fused into GEMM2 epilogue)
__global__ __launch_bounds__(256) void scan_pass2(const float* __restrict__ dp)
{
    float decay = get_decay(dp);
    float dpow = decay;
    #pragma unroll
    for (int i = 0; i < 5; i++) dpow *= dpow;  // decay^32 (CHUNK=32)
    int idx = blockIdx.x * 256 + threadIdx.x;  // 0..4095
    int b = idx >> 10;
    int e = idx & 1023;
    float he = 0.0f;
    #pragma unroll 8
    for (int c = 0; c < NCHUNK; c++) {
        size_t off = ((size_t)b * NCHUNK + c) * D_MODEL + e;
        g_cin[off] = he;
        he = fmaf(dpow, he, g_C[off]);
    }
}

__global__ __launch_bounds__(256) void scan_pass3(const float* __restrict__ dp,
                                                  const float* __restrict__ bias,
                                                  float* __restrict__ dst)
{
    float decay = get_decay(dp);
    int c = blockIdx.x;
    int b = blockIdx.y;
    int e4 = threadIdx.x << 2;
    size_t base = ((size_t)(b * SEQ + c * CHUNK)) * D_MODEL + e4;
    const __half* v = g_xh + base;
    float*        o = dst  + base;
    float4 bf = *(const float4*)(bias + e4);
    float4 acc = *(const float4*)(g_cin + ((size_t)b * NCHUNK + c) * D_MODEL + e4);
    #pragma unroll 8
    for (int s = 0; s < CHUNK; s++) {
        uint2 raw = *(const uint2*)(v + (size_t)s * D_MODEL);
        float2 f0 = __half22float2(*(__half2*)&raw.x);
        float2 f1 = __half22float2(*(__half2*)&raw.y);
        acc.x = fmaf(decay, acc.x, f0.x);
        acc.y = fmaf(decay, acc.y, f0.y);
        acc.z = fmaf(decay, acc.z, f1.x);
        acc.w = fmaf(decay, acc.w, f1.y);
        float4 w;
        w.x = acc.x + bf.x;
        w.y = acc.y + bf.y;
        w.z = acc.z + bf.z;
        w.w = acc.w + bf.w;
        *(float4*)(o + (size_t)s * D_MODEL) = w;
    }
}

// ---------------- launch
extern "C" void kernel_launch(void* const* d_in, const int* in_sizes, int n_in,
                              void* d_out, int out_size)
{
    const float* x     = (const float*)d_in[0];
    const float* mask  = (const float*)d_in[1];
    const float* W_up  = (const float*)d_in[2];
    const float* b_up  = (const float*)d_in[3];
    const float* W_f   = (const float*)d_in[4];
    const float* b_f   = (const float*)d_in[5];
    const float* dp    = (const float*)d_in[6];
    float* out = (float*)d_out;

    __half *xh, *uh, *w1h, *w2h;
    cudaGetSymbolAddress((void**)&xh,  g_xh);
    cudaGetSymbolAddress((void**)&uh,  g_uh);
    cudaGetSymbolAddress((void**)&w1h, g_w1h);
    cudaGetSymbolAddress((void**)&w2h, g_w2h);

    cudaFuncSetAttribute(gemm_h, cudaFuncAttributeMaxDynamicSharedMemorySize, SMEM_BYTES);

    dim3 ggrid(D_MODEL / BN, M_TOTAL / BM);   // (8, 128)

    // convert inputs to fp16
    to_half<<<NX / 4 / 256, 256>>>((const float4*)x,    (__half2*)xh,  NX / 4);
    to_half<<<D2 / 4 / 256, 256>>>((const float4*)W_up, (__half2*)w1h, D2 / 4);
    to_half<<<D2 / 4 / 256, 256>>>((const float4*)W_f,  (__half2*)w2h, D2 / 4);

    // u = half((x @ W_up^T + b_up) * mask)
    gemm_h<<<ggrid, 256, SMEM_BYTES>>>(xh, w1h, b_up, mask, uh, nullptr);

    // v = half(u @ W_f^T), fused 32-row chunk sums -> g_C (scan pass1)
    gemm_h<<<ggrid, 256, SMEM_BYTES>>>(uh, w2h, nullptr, nullptr, xh, dp);

    // out = scan(v) + b_f
    scan_pass2<<<16, 256>>>(dp);
    scan_pass3<<<dim3(NCHUNK, BATCH), 256>>>(dp, b_f, out);
}